// round 16
// baseline (speedup 1.0000x reference)
#include <cuda_runtime.h>
#include <cuda_bf16.h>
#include <cstdint>
#include <cstddef>

#define D_MODEL 512
#define NHEAD   8
#define DH      64
#define BATCH   2
#define SEQ     2048
#define NTOK    (BATCH*SEQ)   // 4096
#define NBH     (BATCH*NHEAD) // 16
#define N1      (NTOK*D_MODEL)     // 2,097,152
#define N2      (D_MODEL*D_MODEL)  // 262,144

static const int       OUT_ELEMS  = N1;
static const long long ATTN_ELEMS = (long long)NBH*SEQ*SEQ;

// ---------------- device scratch (allocation-free rule) ----------------
__device__ __align__(16) __nv_bfloat16 g_INh[3*N1], g_INl[3*N1];
__device__ __align__(16) __nv_bfloat16 g_Wh[4*N2],  g_Wl[4*N2];
__device__ __align__(16) __nv_bfloat16 g_Qh[NBH*SEQ*DH], g_Ql[NBH*SEQ*DH];
__device__ __align__(16) __nv_bfloat16 g_Kh[NBH*SEQ*DH], g_Kl[NBH*SEQ*DH];
__device__ __align__(16) __nv_bfloat16 g_Vth[NBH*DH*SEQ], g_Vtl[NBH*DH*SEQ];
__device__ __align__(16) __nv_bfloat16 g_Ah[(size_t)NBH*SEQ*SEQ], g_Al[(size_t)NBH*SEQ*SEQ]; // unnormalized exp hi/lo
__device__ __align__(16) __nv_bfloat16 g_Xh[N1], g_Xl[N1];
__device__ __align__(16) float         g_rowinv[NBH*SEQ];
__device__ __align__(16) float         g_attn_fallback[(size_t)NBH*SEQ*SEQ];

// ---------------- helpers ----------------
__device__ __forceinline__ uint32_t smem_u32(const void* p) {
    uint32_t a;
    asm("{ .reg .u64 t; cvta.to.shared.u64 t, %1; cvt.u32.u64 %0, t; }" : "=r"(a) : "l"(p));
    return a;
}
__device__ __forceinline__ void bf16_split(float v, __nv_bfloat16& hi, __nv_bfloat16& lo) {
    hi = __float2bfloat16(v);
    lo = __float2bfloat16(v - __bfloat162float(hi));
}
__device__ __forceinline__ uint32_t pack2(__nv_bfloat16 a, __nv_bfloat16 b) {
    return (uint32_t)__bfloat16_as_ushort(a) | ((uint32_t)__bfloat16_as_ushort(b) << 16);
}
__device__ __forceinline__ void mma_bf16(float d[4], const uint32_t a[4], const uint32_t b[2]) {
    asm volatile(
        "mma.sync.aligned.m16n8k16.row.col.f32.bf16.bf16.f32 "
        "{%0,%1,%2,%3}, {%4,%5,%6,%7}, {%8,%9}, {%0,%1,%2,%3};\n"
        : "+f"(d[0]), "+f"(d[1]), "+f"(d[2]), "+f"(d[3])
        : "r"(a[0]), "r"(a[1]), "r"(a[2]), "r"(a[3]), "r"(b[0]), "r"(b[1]));
}
__device__ __forceinline__ void ldsm_x4(uint32_t& r0, uint32_t& r1, uint32_t& r2, uint32_t& r3,
                                        uint32_t addr) {
    asm volatile("ldmatrix.sync.aligned.m8n8.x4.shared.b16 {%0,%1,%2,%3}, [%4];"
        : "=r"(r0), "=r"(r1), "=r"(r2), "=r"(r3) : "r"(addr));
}

#define TSTRIDE_B 144
#define TILE_BYTES (128*TSTRIDE_B)    // 18432
#define BTILE64    (64*TSTRIDE_B)     // 9216

#define CP_COMMIT() asm volatile("cp.async.commit_group;" ::: "memory")

__device__ __forceinline__ void cp_tile128(char* dst, const __nv_bfloat16* src, int ld, int tid) {
    const int row = tid >> 3, c = tid & 7;
#pragma unroll
    for (int t = 0; t < 4; t++) {
        uint32_t d = smem_u32(dst + (row + t*32)*TSTRIDE_B + c*16);
        const void* g = src + (size_t)(row + t*32)*ld + c*8;
        asm volatile("cp.async.cg.shared.global [%0], [%1], 16;" :: "r"(d), "l"(g) : "memory");
    }
}
__device__ __forceinline__ void cp_tile64(char* dst, const __nv_bfloat16* src, int ld, int tid) {
    const int row = tid >> 3, c = tid & 7;
#pragma unroll
    for (int t = 0; t < 2; t++) {
        uint32_t d = smem_u32(dst + (row + t*32)*TSTRIDE_B + c*16);
        const void* g = src + (size_t)(row + t*32)*ld + c*8;
        asm volatile("cp.async.cg.shared.global [%0], [%1], 16;" :: "r"(d), "l"(g) : "memory");
    }
}

// ---------------------------------------------------------------------------
// 3-pass (hh + h*lo + lo*h) HMMA with ldmatrix fragment loads.
// ---------------------------------------------------------------------------
template<int NT>
__device__ __forceinline__ void hmma_3pass(
    const char* A0c, const char* A1c, const char* B0c, const char* B1c,
    int i0w, int j0w, float acc[2][NT][4])
{
    const int lane = (threadIdx.x & 31);
    const uint32_t aoff = (uint32_t)(((lane & 7) + ((lane >> 3) & 1)*8)*TSTRIDE_B + (lane >> 4)*16);
    const uint32_t boff = (uint32_t)(((lane & 7) + ((lane >> 4) & 1)*8)*TSTRIDE_B + ((lane >> 3) & 1)*16);
    const uint32_t A0 = smem_u32(A0c) + i0w*TSTRIDE_B + aoff;
    const uint32_t A1 = smem_u32(A1c) + i0w*TSTRIDE_B + aoff;
    const uint32_t B0 = smem_u32(B0c) + j0w*TSTRIDE_B + boff;
    const uint32_t B1 = smem_u32(B1c) + j0w*TSTRIDE_B + boff;

#pragma unroll
    for (int pass = 0; pass < 3; pass++) {
        const uint32_t A = (pass == 2) ? A1 : A0;
        const uint32_t B = (pass == 1) ? B1 : B0;
#pragma unroll
        for (int ks = 0; ks < 4; ks++) {
            uint32_t a[2][4];
#pragma unroll
            for (int mt = 0; mt < 2; mt++)
                ldsm_x4(a[mt][0], a[mt][1], a[mt][2], a[mt][3],
                        A + mt*16*TSTRIDE_B + ks*32);
#pragma unroll
            for (int p = 0; p < NT/2; p++) {
                uint32_t b0, b1, b2, b3;
                ldsm_x4(b0, b1, b2, b3, B + p*16*TSTRIDE_B + ks*32);
                uint32_t bbA[2] = { b0, b1 };
                uint32_t bbB[2] = { b2, b3 };
                mma_bf16(acc[0][2*p+0], a[0], bbA);
                mma_bf16(acc[1][2*p+0], a[1], bbA);
                mma_bf16(acc[0][2*p+1], a[0], bbB);
                mma_bf16(acc[1][2*p+1], a[1], bbB);
            }
        }
    }
}

// ---------------------------------------------------------------------------
// Split kernel
// ---------------------------------------------------------------------------
__global__ void __launch_bounds__(256)
split_kernel(const float* __restrict__ q, const float* __restrict__ k, const float* __restrict__ v,
             const float* __restrict__ Wq, const float* __restrict__ Wk,
             const float* __restrict__ Wv, const float* __restrict__ Wo)
{
    const int which = blockIdx.y;
    const float* src; __nv_bfloat16* dh; __nv_bfloat16* dl; int count;
    if (which < 3) {
        src = (which == 0) ? q : (which == 1) ? k : v;
        dh = g_INh + (size_t)which*N1; dl = g_INl + (size_t)which*N1; count = N1/4;
    } else {
        const int w = which - 3;
        src = (w == 0) ? Wq : (w == 1) ? Wk : (w == 2) ? Wv : Wo;
        dh = g_Wh + (size_t)w*N2; dl = g_Wl + (size_t)w*N2; count = N2/4;
    }
    for (int i = blockIdx.x*blockDim.x + threadIdx.x; i < count; i += gridDim.x*blockDim.x) {
        float4 x = reinterpret_cast<const float4*>(src)[i];
        __nv_bfloat16 h0,l0,h1,l1,h2,l2,h3,l3;
        bf16_split(x.x,h0,l0); bf16_split(x.y,h1,l1);
        bf16_split(x.z,h2,l2); bf16_split(x.w,h3,l3);
        uint2 ph, pl;
        ph.x = pack2(h0,h1); ph.y = pack2(h2,h3);
        pl.x = pack2(l0,l1); pl.y = pack2(l2,l3);
        reinterpret_cast<uint2*>(dh)[i] = ph;
        reinterpret_cast<uint2*>(dl)[i] = pl;
    }
}

// ---------------------------------------------------------------------------
// QKV projection (R13: K=64 chunks, stride 144; V transpose-staged epilogue)
// ---------------------------------------------------------------------------
#define VSTRIDE 272
#define VTILE   (128*VSTRIDE)          // 34816
#define PROJ_SMEM (8*TILE_BYTES)       // 147456
__global__ void __launch_bounds__(256)
qkv_proj_kernel(const float* __restrict__ bq, const float* __restrict__ bk,
                const float* __restrict__ bv)
{
    extern __shared__ char smem[];
    const int tid = threadIdx.x, wid = tid >> 5;
    const int lane = tid & 31, gid = lane >> 2, tig = lane & 3;
    const int z = blockIdx.z;
    const int m0 = blockIdx.y*128, n0 = blockIdx.x*128;
    const int i0w = (wid & 3)*32, j0w = (wid >> 2)*64;

    const __nv_bfloat16* Ah = g_INh + (size_t)z*N1 + (size_t)m0*D_MODEL;
    const __nv_bfloat16* Al = g_INl + (size_t)z*N1 + (size_t)m0*D_MODEL;
    const __nv_bfloat16* Bh = g_Wh  + (size_t)z*N2 + (size_t)n0*D_MODEL;
    const __nv_bfloat16* Bl = g_Wl  + (size_t)z*N2 + (size_t)n0*D_MODEL;
    const float* bias = (z == 0) ? bq : (z == 1) ? bk : bv;

    float acc[2][8][4];
#pragma unroll
    for (int mt = 0; mt < 2; mt++)
#pragma unroll
        for (int nt = 0; nt < 8; nt++)
#pragma unroll
            for (int q = 0; q < 4; q++) acc[mt][nt][q] = 0.f;

    {
        char* buf = smem;
        cp_tile128(buf,                Ah, D_MODEL, tid);
        cp_tile128(buf +   TILE_BYTES, Al, D_MODEL, tid);
        cp_tile128(buf + 2*TILE_BYTES, Bh, D_MODEL, tid);
        cp_tile128(buf + 3*TILE_BYTES, Bl, D_MODEL, tid);
        CP_COMMIT();
    }
    for (int ch = 0; ch < 8; ch++) {
        if (ch < 7) {
            char* buf = smem + ((ch+1)&1)*(4*TILE_BYTES);
            const int k0 = (ch+1)*64;
            cp_tile128(buf,                Ah + k0, D_MODEL, tid);
            cp_tile128(buf +   TILE_BYTES, Al + k0, D_MODEL, tid);
            cp_tile128(buf + 2*TILE_BYTES, Bh + k0, D_MODEL, tid);
            cp_tile128(buf + 3*TILE_BYTES, Bl + k0, D_MODEL, tid);
            CP_COMMIT();
            asm volatile("cp.async.wait_group 1;" ::: "memory");
        } else {
            asm volatile("cp.async.wait_group 0;" ::: "memory");
        }
        __syncthreads();
        char* buf = smem + (ch&1)*(4*TILE_BYTES);
        hmma_3pass<8>(buf, buf + TILE_BYTES, buf + 2*TILE_BYTES, buf + 3*TILE_BYTES,
                      i0w, j0w, acc);
        __syncthreads();
    }

    if (z < 2) {
#pragma unroll
        for (int nt = 0; nt < 8; nt++) {
            const int col = n0 + j0w + nt*8 + tig*2;
            const int h = col >> 6, d = col & 63;
            const float b0v = bias[col], b1v = bias[col+1];
#pragma unroll
            for (int mt = 0; mt < 2; mt++) {
#pragma unroll
                for (int half = 0; half < 2; half++) {
                    const int token = m0 + i0w + mt*16 + gid + half*8;
                    const int b = token >> 11, s = token & 2047;
                    float v0 = acc[mt][nt][half*2+0] + b0v;
                    float v1 = acc[mt][nt][half*2+1] + b1v;
                    __nv_bfloat16 h0,l0,h1,l1;
                    bf16_split(v0,h0,l0); bf16_split(v1,h1,l1);
                    size_t o = ((size_t)(b*NHEAD + h)*SEQ + s)*DH + d;
                    if (z == 0) {
                        *reinterpret_cast<uint32_t*>(g_Qh + o) = pack2(h0,h1);
                        *reinterpret_cast<uint32_t*>(g_Ql + o) = pack2(l0,l1);
                    } else {
                        *reinterpret_cast<uint32_t*>(g_Kh + o) = pack2(h0,h1);
                        *reinterpret_cast<uint32_t*>(g_Kl + o) = pack2(l0,l1);
                    }
                }
            }
        }
    } else {
        char* sVh = smem;
        char* sVl = smem + VTILE;
#pragma unroll
        for (int nt = 0; nt < 8; nt++) {
            const int colL = j0w + nt*8 + tig*2;
            const int col = n0 + colL;
            const float b0v = bias[col], b1v = bias[col+1];
#pragma unroll
            for (int mt = 0; mt < 2; mt++) {
#pragma unroll
                for (int half = 0; half < 2; half++) {
                    const int tok = i0w + mt*16 + gid + half*8;
                    float v0 = acc[mt][nt][half*2+0] + b0v;
                    float v1 = acc[mt][nt][half*2+1] + b1v;
                    __nv_bfloat16 h0,l0,h1,l1;
                    bf16_split(v0,h0,l0); bf16_split(v1,h1,l1);
                    *reinterpret_cast<__nv_bfloat16*>(sVh + colL*VSTRIDE + tok*2)     = h0;
                    *reinterpret_cast<__nv_bfloat16*>(sVh + (colL+1)*VSTRIDE + tok*2) = h1;
                    *reinterpret_cast<__nv_bfloat16*>(sVl + colL*VSTRIDE + tok*2)     = l0;
                    *reinterpret_cast<__nv_bfloat16*>(sVl + (colL+1)*VSTRIDE + tok*2) = l1;
                }
            }
        }
        __syncthreads();
        const int b  = m0 >> 11, s0 = m0 & 2047;
        const int rsub = tid >> 4, cw = tid & 15;
#pragma unroll
        for (int it = 0; it < 8; it++) {
            const int rl = it*16 + rsub;
            const int col = n0 + rl;
            const int h = col >> 6, d = col & 63;
            uint4 vh = *reinterpret_cast<uint4*>(sVh + rl*VSTRIDE + cw*16);
            uint4 vl = *reinterpret_cast<uint4*>(sVl + rl*VSTRIDE + cw*16);
            size_t o = ((size_t)(b*NHEAD + h)*DH + d)*SEQ + s0 + cw*8;
            *reinterpret_cast<uint4*>(g_Vth + o) = vh;
            *reinterpret_cast<uint4*>(g_Vtl + o) = vl;
        }
    }
}

// ---------------------------------------------------------------------------
// Output projection (R13, unchanged)
// ---------------------------------------------------------------------------
__global__ void __launch_bounds__(256)
oproj_kernel(const float* __restrict__ bo, float* __restrict__ out)
{
    extern __shared__ char smem[];
    const int tid = threadIdx.x, wid = tid >> 5;
    const int lane = tid & 31, gid = lane >> 2, tig = lane & 3;
    const int m0 = blockIdx.y*128, n0 = blockIdx.x*128;
    const int i0w = (wid & 3)*32, j0w = (wid >> 2)*64;

    const __nv_bfloat16* Ah = g_Xh + (size_t)m0*D_MODEL;
    const __nv_bfloat16* Al = g_Xl + (size_t)m0*D_MODEL;
    const __nv_bfloat16* Bh = g_Wh + (size_t)3*N2 + (size_t)n0*D_MODEL;
    const __nv_bfloat16* Bl = g_Wl + (size_t)3*N2 + (size_t)n0*D_MODEL;

    float acc[2][8][4];
#pragma unroll
    for (int mt = 0; mt < 2; mt++)
#pragma unroll
        for (int nt = 0; nt < 8; nt++)
#pragma unroll
            for (int q = 0; q < 4; q++) acc[mt][nt][q] = 0.f;

    {
        char* buf = smem;
        cp_tile128(buf,                Ah, D_MODEL, tid);
        cp_tile128(buf +   TILE_BYTES, Al, D_MODEL, tid);
        cp_tile128(buf + 2*TILE_BYTES, Bh, D_MODEL, tid);
        cp_tile128(buf + 3*TILE_BYTES, Bl, D_MODEL, tid);
        CP_COMMIT();
    }
    for (int ch = 0; ch < 8; ch++) {
        if (ch < 7) {
            char* buf = smem + ((ch+1)&1)*(4*TILE_BYTES);
            const int k0 = (ch+1)*64;
            cp_tile128(buf,                Ah + k0, D_MODEL, tid);
            cp_tile128(buf +   TILE_BYTES, Al + k0, D_MODEL, tid);
            cp_tile128(buf + 2*TILE_BYTES, Bh + k0, D_MODEL, tid);
            cp_tile128(buf + 3*TILE_BYTES, Bl + k0, D_MODEL, tid);
            CP_COMMIT();
            asm volatile("cp.async.wait_group 1;" ::: "memory");
        } else {
            asm volatile("cp.async.wait_group 0;" ::: "memory");
        }
        __syncthreads();
        char* buf = smem + (ch&1)*(4*TILE_BYTES);
        hmma_3pass<8>(buf, buf + TILE_BYTES, buf + 2*TILE_BYTES, buf + 3*TILE_BYTES,
                      i0w, j0w, acc);
        __syncthreads();
    }

#pragma unroll
    for (int nt = 0; nt < 8; nt++) {
        const int col = n0 + j0w + nt*8 + tig*2;
        const float b0v = bo[col], b1v = bo[col+1];
#pragma unroll
        for (int mt = 0; mt < 2; mt++) {
#pragma unroll
            for (int half = 0; half < 2; half++) {
                const int row = m0 + i0w + mt*16 + gid + half*8;
                float2 o;
                o.x = acc[mt][nt][half*2+0] + b0v;
                o.y = acc[mt][nt][half*2+1] + b1v;
                *reinterpret_cast<float2*>(out + (size_t)row*D_MODEL + col) = o;
            }
        }
    }
}

// ---------------------------------------------------------------------------
// Score kernel (R13, unchanged): masked, scaled fp32 scores into attn buffer.
// ---------------------------------------------------------------------------
#define SCORE_SMEM (4*TILE_BYTES)
__global__ void __launch_bounds__(256)
score_kernel(const int* __restrict__ mask, float* attn_arg)
{
    float* attn = attn_arg ? attn_arg : g_attn_fallback;
    extern __shared__ char smem[];
    char* sQ0 = smem;
    char* sQ1 = smem + TILE_BYTES;
    char* sK0 = smem + 2*TILE_BYTES;
    char* sK1 = smem + 3*TILE_BYTES;

    const int tid = threadIdx.x, wid = tid >> 5;
    const int lane = tid & 31, gid = lane >> 2, tig = lane & 3;
    const int bh = blockIdx.z, b = bh >> 3;
    const int m0 = blockIdx.y*128, n0 = blockIdx.x*128;
    const int i0w = (wid & 3)*32, j0w = (wid >> 2)*64;

    cp_tile128(sQ0, g_Qh + ((size_t)bh*SEQ + m0)*DH, DH, tid);
    cp_tile128(sQ1, g_Ql + ((size_t)bh*SEQ + m0)*DH, DH, tid);
    cp_tile128(sK0, g_Kh + ((size_t)bh*SEQ + n0)*DH, DH, tid);
    cp_tile128(sK1, g_Kl + ((size_t)bh*SEQ + n0)*DH, DH, tid);
    CP_COMMIT();
    asm volatile("cp.async.wait_group 0;" ::: "memory");
    __syncthreads();

    float acc[2][8][4];
#pragma unroll
    for (int mt = 0; mt < 2; mt++)
#pragma unroll
        for (int nt = 0; nt < 8; nt++)
#pragma unroll
            for (int q = 0; q < 4; q++) acc[mt][nt][q] = 0.f;

    hmma_3pass<8>(sQ0, sQ1, sK0, sK1, i0w, j0w, acc);

#pragma unroll
    for (int nt = 0; nt < 8; nt++) {
        const int col = n0 + j0w + nt*8 + tig*2;
        const int mv0 = __ldg(mask + b*SEQ + col);
        const int mv1 = __ldg(mask + b*SEQ + col + 1);
#pragma unroll
        for (int mt = 0; mt < 2; mt++) {
#pragma unroll
            for (int half = 0; half < 2; half++) {
                const int row = m0 + i0w + mt*16 + gid + half*8;
                float v0 = acc[mt][nt][half*2+0] * 0.125f;
                float v1 = acc[mt][nt][half*2+1] * 0.125f;
                if (mv0 == 0) v0 = -1.0e9f;
                if (mv1 == 0) v1 = -1.0e9f;
                float2 o; o.x = v0; o.y = v1;
                *reinterpret_cast<float2*>(attn + ((size_t)bh*SEQ + row)*SEQ + col) = o;
            }
        }
    }
}

// ---------------------------------------------------------------------------
// Softmax stats: reads scores, computes max/sum, writes UNNORMALIZED exp bf16
// hi/lo to g_Ah/g_Al and 1/sum to g_rowinv. Does NOT write attn (pv does).
// ---------------------------------------------------------------------------
__global__ void __launch_bounds__(256)
softmax_kernel(const float* attn_arg)
{
    const float* attn = attn_arg ? attn_arg : g_attn_fallback;
    __shared__ float red[8];
    const size_t row = blockIdx.x;
    const float* p = attn + row * (size_t)SEQ;
    const int tid = threadIdx.x;

    float4 v0 = reinterpret_cast<const float4*>(p)[2*tid + 0];
    float4 v1 = reinterpret_cast<const float4*>(p)[2*tid + 1];

    float m = fmaxf(fmaxf(fmaxf(v0.x,v0.y), fmaxf(v0.z,v0.w)),
                    fmaxf(fmaxf(v1.x,v1.y), fmaxf(v1.z,v1.w)));
#pragma unroll
    for (int o = 16; o; o >>= 1) m = fmaxf(m, __shfl_xor_sync(0xffffffffu, m, o));
    if ((tid & 31) == 0) red[tid >> 5] = m;
    __syncthreads();
    m = red[0];
#pragma unroll
    for (int w = 1; w < 8; w++) m = fmaxf(m, red[w]);
    __syncthreads();

    v0.x = __expf(v0.x - m); v0.y = __expf(v0.y - m);
    v0.z = __expf(v0.z - m); v0.w = __expf(v0.w - m);
    v1.x = __expf(v1.x - m); v1.y = __expf(v1.y - m);
    v1.z = __expf(v1.z - m); v1.w = __expf(v1.w - m);

    float s = v0.x + v0.y + v0.z + v0.w + v1.x + v1.y + v1.z + v1.w;
#pragma unroll
    for (int o = 16; o; o >>= 1) s += __shfl_xor_sync(0xffffffffu, s, o);
    if ((tid & 31) == 0) red[tid >> 5] = s;
    __syncthreads();
    s = red[0];
#pragma unroll
    for (int w = 1; w < 8; w++) s += red[w];

    if (tid == 0) g_rowinv[row] = 1.0f / s;

    float vf[8] = { v0.x, v0.y, v0.z, v0.w, v1.x, v1.y, v1.z, v1.w };
    __nv_bfloat16 hb[8], lb[8];
#pragma unroll
    for (int e = 0; e < 8; e++) bf16_split(vf[e], hb[e], lb[e]);
    size_t off = row * (size_t)SEQ + tid*8;
    *reinterpret_cast<uint4*>(g_Ah + off) = *reinterpret_cast<uint4*>(hb);
    *reinterpret_cast<uint4*>(g_Al + off) = *reinterpret_cast<uint4*>(lb);
}

// ---------------------------------------------------------------------------
// PV kernel: A = unnormalized exp hi/lo. Per chunk, also writes the
// normalized attn fp32 from the staged smem tiles (fire-and-forget stores).
// Epilogue scales acc by g_rowinv.
// ---------------------------------------------------------------------------
#define PVBUF   (2*TILE_BYTES + 2*BTILE64)   // 55296
#define PV_SMEM (2*PVBUF)                     // 110592
__global__ void __launch_bounds__(256)
pv_kernel(float* attn_arg)
{
    float* attn = attn_arg ? attn_arg : g_attn_fallback;
    extern __shared__ char smem[];
    const int tid = threadIdx.x, wid = tid >> 5;
    const int lane = tid & 31, gid = lane >> 2, tig = lane & 3;
    const int bh = blockIdx.y, b = bh >> 3, h = bh & 7;
    const int m0 = blockIdx.x * 128;
    const int i0w = (wid & 3)*32, d0w = (wid >> 2)*32;

    const __nv_bfloat16* Ah = g_Ah + ((size_t)bh*SEQ + m0)*SEQ;
    const __nv_bfloat16* Al = g_Al + ((size_t)bh*SEQ + m0)*SEQ;
    const __nv_bfloat16* Bh = g_Vth + (size_t)bh*DH*SEQ;
    const __nv_bfloat16* Bl = g_Vtl + (size_t)bh*DH*SEQ;

    // attn-store mapping: thread -> (row = tid>>1, col-half = tid&1)
    const int srow = tid >> 1, shalf = tid & 1;
    const float sinv = g_rowinv[bh*SEQ + m0 + srow];
    float* sdst = attn + ((size_t)bh*SEQ + m0 + srow)*SEQ + shalf*32;

    float acc[2][4][4];
#pragma unroll
    for (int mt = 0; mt < 2; mt++)
#pragma unroll
        for (int nt = 0; nt < 4; nt++)
#pragma unroll
            for (int q = 0; q < 4; q++) acc[mt][nt][q] = 0.f;

    {
        char* buf = smem;
        cp_tile128(buf,                         Ah, SEQ, tid);
        cp_tile128(buf + TILE_BYTES,            Al, SEQ, tid);
        cp_tile64 (buf + 2*TILE_BYTES,           Bh, SEQ, tid);
        cp_tile64 (buf + 2*TILE_BYTES + BTILE64, Bl, SEQ, tid);
        CP_COMMIT();
    }
    for (int ch = 0; ch < 32; ch++) {
        if (ch < 31) {
            char* buf = smem + ((ch+1)&1)*PVBUF;
            const int j0 = (ch+1)*64;
            cp_tile128(buf,                         Ah + j0, SEQ, tid);
            cp_tile128(buf + TILE_BYTES,            Al + j0, SEQ, tid);
            cp_tile64 (buf + 2*TILE_BYTES,           Bh + j0, SEQ, tid);
            cp_tile64 (buf + 2*TILE_BYTES + BTILE64, Bl + j0, SEQ, tid);
            CP_COMMIT();
            asm volatile("cp.async.wait_group 1;" ::: "memory");
        } else {
            asm volatile("cp.async.wait_group 0;" ::: "memory");
        }
        __syncthreads();
        char* buf = smem + (ch&1)*PVBUF;

        // write normalized attn for this chunk from staged smem (read-only on tiles)
        {
            const char* ah = buf + srow*TSTRIDE_B + shalf*64;
            const char* al = buf + TILE_BYTES + srow*TSTRIDE_B + shalf*64;
            float* dst = sdst + (size_t)ch*64;
#pragma unroll
            for (int q = 0; q < 4; q++) {
                uint4 vh = *reinterpret_cast<const uint4*>(ah + q*16);
                uint4 vl = *reinterpret_cast<const uint4*>(al + q*16);
                const uint32_t* hp = reinterpret_cast<const uint32_t*>(&vh);
                const uint32_t* lp = reinterpret_cast<const uint32_t*>(&vl);
                float o[8];
#pragma unroll
                for (int e = 0; e < 4; e++) {
                    __nv_bfloat162 h2 = *reinterpret_cast<const __nv_bfloat162*>(hp + e);
                    __nv_bfloat162 l2 = *reinterpret_cast<const __nv_bfloat162*>(lp + e);
                    o[2*e+0] = (__bfloat162float(h2.x) + __bfloat162float(l2.x)) * sinv;
                    o[2*e+1] = (__bfloat162float(h2.y) + __bfloat162float(l2.y)) * sinv;
                }
                *reinterpret_cast<float4*>(dst + q*8)     = make_float4(o[0], o[1], o[2], o[3]);
                *reinterpret_cast<float4*>(dst + q*8 + 4) = make_float4(o[4], o[5], o[6], o[7]);
            }
        }

        hmma_3pass<4>(buf, buf + TILE_BYTES, buf + 2*TILE_BYTES, buf + 2*TILE_BYTES + BTILE64,
                      i0w, d0w, acc);
        __syncthreads();
    }

    float invr[2][2];
#pragma unroll
    for (int mt = 0; mt < 2; mt++)
#pragma unroll
        for (int half = 0; half < 2; half++) {
            const int row = m0 + i0w + mt*16 + gid + half*8;
            invr[mt][half] = g_rowinv[bh*SEQ + row];
        }

#pragma unroll
    for (int nt = 0; nt < 4; nt++) {
        const int d = d0w + nt*8 + tig*2;
#pragma unroll
        for (int mt = 0; mt < 2; mt++) {
#pragma unroll
            for (int half = 0; half < 2; half++) {
                const int row = m0 + i0w + mt*16 + gid + half*8;
                float v0 = acc[mt][nt][half*2+0] * invr[mt][half];
                float v1 = acc[mt][nt][half*2+1] * invr[mt][half];
                __nv_bfloat16 h0,l0,h1,l1;
                bf16_split(v0,h0,l0); bf16_split(v1,h1,l1);
                size_t o = ((size_t)(b*SEQ + row))*D_MODEL + h*DH + d;
                *reinterpret_cast<uint32_t*>(g_Xh + o) = pack2(h0,h1);
                *reinterpret_cast<uint32_t*>(g_Xl + o) = pack2(l0,l1);
            }
        }
    }
}

// ---------------------------------------------------------------------------
extern "C" void kernel_launch(void* const* d_in, const int* in_sizes, int n_in,
                              void* d_out, int out_size)
{
    const float* query = (const float*)d_in[0];
    const float* key   = (const float*)d_in[1];
    const float* value = (const float*)d_in[2];
    const int*   mask  = (const int*)  d_in[3];
    const float* Wq    = (const float*)d_in[4];
    const float* bq    = (const float*)d_in[5];
    const float* Wk    = (const float*)d_in[6];
    const float* bk    = (const float*)d_in[7];
    const float* Wv    = (const float*)d_in[8];
    const float* bv    = (const float*)d_in[9];
    const float* Wo    = (const float*)d_in[10];
    const float* bo    = (const float*)d_in[11];

    float* out = (float*)d_out;
    float* attn_arg = ((long long)out_size >= (long long)OUT_ELEMS + ATTN_ELEMS)
                      ? (out + OUT_ELEMS) : nullptr;

    cudaFuncSetAttribute(qkv_proj_kernel, cudaFuncAttributeMaxDynamicSharedMemorySize, PROJ_SMEM);
    cudaFuncSetAttribute(oproj_kernel,    cudaFuncAttributeMaxDynamicSharedMemorySize, PROJ_SMEM);
    cudaFuncSetAttribute(score_kernel,    cudaFuncAttributeMaxDynamicSharedMemorySize, SCORE_SMEM);
    cudaFuncSetAttribute(pv_kernel,       cudaFuncAttributeMaxDynamicSharedMemorySize, PV_SMEM);

    dim3 blk(256);
    split_kernel   <<<dim3(256, 7), blk>>>(query, key, value, Wq, Wk, Wv, Wo);
    qkv_proj_kernel<<<dim3(4, 32, 3), blk, PROJ_SMEM>>>(bq, bk, bv);
    score_kernel   <<<dim3(16, 16, 16), blk, SCORE_SMEM>>>(mask, attn_arg);
    softmax_kernel <<<dim3(NBH*SEQ), blk>>>(attn_arg);
    pv_kernel      <<<dim3(16, 16), blk, PV_SMEM>>>(attn_arg);
    oproj_kernel   <<<dim3(4, 32), blk, PROJ_SMEM>>>(bo, out);
}

// round 17
// speedup vs baseline: 1.1234x; 1.1234x over previous
#include <cuda_runtime.h>
#include <cuda_bf16.h>
#include <cstdint>
#include <cstddef>

#define D_MODEL 512
#define NHEAD   8
#define DH      64
#define BATCH   2
#define SEQ     2048
#define NTOK    (BATCH*SEQ)   // 4096
#define NBH     (BATCH*NHEAD) // 16
#define N1      (NTOK*D_MODEL)     // 2,097,152
#define N2      (D_MODEL*D_MODEL)  // 262,144

static const int       OUT_ELEMS  = N1;
static const long long ATTN_ELEMS = (long long)NBH*SEQ*SEQ;

// ---------------- device scratch (allocation-free rule) ----------------
__device__ __align__(16) __nv_bfloat16 g_INh[3*N1], g_INl[3*N1];
__device__ __align__(16) __nv_bfloat16 g_Wh[4*N2],  g_Wl[4*N2];
__device__ __align__(16) __nv_bfloat16 g_Qh[NBH*SEQ*DH], g_Ql[NBH*SEQ*DH];
__device__ __align__(16) __nv_bfloat16 g_Kh[NBH*SEQ*DH], g_Kl[NBH*SEQ*DH];
__device__ __align__(16) __nv_bfloat16 g_Vth[NBH*DH*SEQ], g_Vtl[NBH*DH*SEQ];
__device__ __align__(16) __nv_bfloat16 g_Ah[(size_t)NBH*SEQ*SEQ], g_Al[(size_t)NBH*SEQ*SEQ];
__device__ __align__(16) __nv_bfloat16 g_Xh[N1], g_Xl[N1];
__device__ __align__(16) float         g_attn_fallback[(size_t)NBH*SEQ*SEQ];

// ---------------- helpers ----------------
__device__ __forceinline__ uint32_t smem_u32(const void* p) {
    uint32_t a;
    asm("{ .reg .u64 t; cvta.to.shared.u64 t, %1; cvt.u32.u64 %0, t; }" : "=r"(a) : "l"(p));
    return a;
}
__device__ __forceinline__ void bf16_split(float v, __nv_bfloat16& hi, __nv_bfloat16& lo) {
    hi = __float2bfloat16(v);
    lo = __float2bfloat16(v - __bfloat162float(hi));
}
__device__ __forceinline__ uint32_t pack2(__nv_bfloat16 a, __nv_bfloat16 b) {
    return (uint32_t)__bfloat16_as_ushort(a) | ((uint32_t)__bfloat16_as_ushort(b) << 16);
}
__device__ __forceinline__ void mma_bf16(float d[4], const uint32_t a[4], const uint32_t b[2]) {
    asm volatile(
        "mma.sync.aligned.m16n8k16.row.col.f32.bf16.bf16.f32 "
        "{%0,%1,%2,%3}, {%4,%5,%6,%7}, {%8,%9}, {%0,%1,%2,%3};\n"
        : "+f"(d[0]), "+f"(d[1]), "+f"(d[2]), "+f"(d[3])
        : "r"(a[0]), "r"(a[1]), "r"(a[2]), "r"(a[3]), "r"(b[0]), "r"(b[1]));
}
__device__ __forceinline__ void ldsm_x4(uint32_t& r0, uint32_t& r1, uint32_t& r2, uint32_t& r3,
                                        uint32_t addr) {
    asm volatile("ldmatrix.sync.aligned.m8n8.x4.shared.b16 {%0,%1,%2,%3}, [%4];"
        : "=r"(r0), "=r"(r1), "=r"(r2), "=r"(r3) : "r"(addr));
}

#define TSTRIDE_B 144
#define TILE_BYTES (128*TSTRIDE_B)    // 18432
#define BTILE64    (64*TSTRIDE_B)     // 9216

#define CP_COMMIT() asm volatile("cp.async.commit_group;" ::: "memory")

__device__ __forceinline__ void cp_tile128(char* dst, const __nv_bfloat16* src, int ld, int tid) {
    const int row = tid >> 3, c = tid & 7;
#pragma unroll
    for (int t = 0; t < 4; t++) {
        uint32_t d = smem_u32(dst + (row + t*32)*TSTRIDE_B + c*16);
        const void* g = src + (size_t)(row + t*32)*ld + c*8;
        asm volatile("cp.async.cg.shared.global [%0], [%1], 16;" :: "r"(d), "l"(g) : "memory");
    }
}
__device__ __forceinline__ void cp_tile64(char* dst, const __nv_bfloat16* src, int ld, int tid) {
    const int row = tid >> 3, c = tid & 7;
#pragma unroll
    for (int t = 0; t < 2; t++) {
        uint32_t d = smem_u32(dst + (row + t*32)*TSTRIDE_B + c*16);
        const void* g = src + (size_t)(row + t*32)*ld + c*8;
        asm volatile("cp.async.cg.shared.global [%0], [%1], 16;" :: "r"(d), "l"(g) : "memory");
    }
}

// ---------------------------------------------------------------------------
// 3-pass (hh + h*lo + lo*h) HMMA with ldmatrix fragment loads.
// ---------------------------------------------------------------------------
template<int NT>
__device__ __forceinline__ void hmma_3pass(
    const char* A0c, const char* A1c, const char* B0c, const char* B1c,
    int i0w, int j0w, float acc[2][NT][4])
{
    const int lane = (threadIdx.x & 31);
    const uint32_t aoff = (uint32_t)(((lane & 7) + ((lane >> 3) & 1)*8)*TSTRIDE_B + (lane >> 4)*16);
    const uint32_t boff = (uint32_t)(((lane & 7) + ((lane >> 4) & 1)*8)*TSTRIDE_B + ((lane >> 3) & 1)*16);
    const uint32_t A0 = smem_u32(A0c) + i0w*TSTRIDE_B + aoff;
    const uint32_t A1 = smem_u32(A1c) + i0w*TSTRIDE_B + aoff;
    const uint32_t B0 = smem_u32(B0c) + j0w*TSTRIDE_B + boff;
    const uint32_t B1 = smem_u32(B1c) + j0w*TSTRIDE_B + boff;

#pragma unroll
    for (int pass = 0; pass < 3; pass++) {
        const uint32_t A = (pass == 2) ? A1 : A0;
        const uint32_t B = (pass == 1) ? B1 : B0;
#pragma unroll
        for (int ks = 0; ks < 4; ks++) {
            uint32_t a[2][4];
#pragma unroll
            for (int mt = 0; mt < 2; mt++)
                ldsm_x4(a[mt][0], a[mt][1], a[mt][2], a[mt][3],
                        A + mt*16*TSTRIDE_B + ks*32);
#pragma unroll
            for (int p = 0; p < NT/2; p++) {
                uint32_t b0, b1, b2, b3;
                ldsm_x4(b0, b1, b2, b3, B + p*16*TSTRIDE_B + ks*32);
                uint32_t bbA[2] = { b0, b1 };
                uint32_t bbB[2] = { b2, b3 };
                mma_bf16(acc[0][2*p+0], a[0], bbA);
                mma_bf16(acc[1][2*p+0], a[1], bbA);
                mma_bf16(acc[0][2*p+1], a[0], bbB);
                mma_bf16(acc[1][2*p+1], a[1], bbB);
            }
        }
    }
}

// ---------------------------------------------------------------------------
// Split kernel
// ---------------------------------------------------------------------------
__global__ void __launch_bounds__(256)
split_kernel(const float* __restrict__ q, const float* __restrict__ k, const float* __restrict__ v,
             const float* __restrict__ Wq, const float* __restrict__ Wk,
             const float* __restrict__ Wv, const float* __restrict__ Wo)
{
    const int which = blockIdx.y;
    const float* src; __nv_bfloat16* dh; __nv_bfloat16* dl; int count;
    if (which < 3) {
        src = (which == 0) ? q : (which == 1) ? k : v;
        dh = g_INh + (size_t)which*N1; dl = g_INl + (size_t)which*N1; count = N1/4;
    } else {
        const int w = which - 3;
        src = (w == 0) ? Wq : (w == 1) ? Wk : (w == 2) ? Wv : Wo;
        dh = g_Wh + (size_t)w*N2; dl = g_Wl + (size_t)w*N2; count = N2/4;
    }
    for (int i = blockIdx.x*blockDim.x + threadIdx.x; i < count; i += gridDim.x*blockDim.x) {
        float4 x = reinterpret_cast<const float4*>(src)[i];
        __nv_bfloat16 h0,l0,h1,l1,h2,l2,h3,l3;
        bf16_split(x.x,h0,l0); bf16_split(x.y,h1,l1);
        bf16_split(x.z,h2,l2); bf16_split(x.w,h3,l3);
        uint2 ph, pl;
        ph.x = pack2(h0,h1); ph.y = pack2(h2,h3);
        pl.x = pack2(l0,l1); pl.y = pack2(l2,l3);
        reinterpret_cast<uint2*>(dh)[i] = ph;
        reinterpret_cast<uint2*>(dl)[i] = pl;
    }
}

// ---------------------------------------------------------------------------
// QKV projection. z==2 (V): transpose-stage in smem, coalesced drain.
// ---------------------------------------------------------------------------
#define VSTRIDE 272
#define VTILE   (128*VSTRIDE)          // 34816
#define PROJ_SMEM (8*TILE_BYTES)       // 147456
__global__ void __launch_bounds__(256)
qkv_proj_kernel(const float* __restrict__ bq, const float* __restrict__ bk,
                const float* __restrict__ bv)
{
    extern __shared__ char smem[];
    const int tid = threadIdx.x, wid = tid >> 5;
    const int lane = tid & 31, gid = lane >> 2, tig = lane & 3;
    const int z = blockIdx.z;
    const int m0 = blockIdx.y*128, n0 = blockIdx.x*128;
    const int i0w = (wid & 3)*32, j0w = (wid >> 2)*64;

    const __nv_bfloat16* Ah = g_INh + (size_t)z*N1 + (size_t)m0*D_MODEL;
    const __nv_bfloat16* Al = g_INl + (size_t)z*N1 + (size_t)m0*D_MODEL;
    const __nv_bfloat16* Bh = g_Wh  + (size_t)z*N2 + (size_t)n0*D_MODEL;
    const __nv_bfloat16* Bl = g_Wl  + (size_t)z*N2 + (size_t)n0*D_MODEL;
    const float* bias = (z == 0) ? bq : (z == 1) ? bk : bv;

    float acc[2][8][4];
#pragma unroll
    for (int mt = 0; mt < 2; mt++)
#pragma unroll
        for (int nt = 0; nt < 8; nt++)
#pragma unroll
            for (int q = 0; q < 4; q++) acc[mt][nt][q] = 0.f;

    {
        char* buf = smem;
        cp_tile128(buf,                Ah, D_MODEL, tid);
        cp_tile128(buf +   TILE_BYTES, Al, D_MODEL, tid);
        cp_tile128(buf + 2*TILE_BYTES, Bh, D_MODEL, tid);
        cp_tile128(buf + 3*TILE_BYTES, Bl, D_MODEL, tid);
        CP_COMMIT();
    }
    for (int ch = 0; ch < 8; ch++) {
        if (ch < 7) {
            char* buf = smem + ((ch+1)&1)*(4*TILE_BYTES);
            const int k0 = (ch+1)*64;
            cp_tile128(buf,                Ah + k0, D_MODEL, tid);
            cp_tile128(buf +   TILE_BYTES, Al + k0, D_MODEL, tid);
            cp_tile128(buf + 2*TILE_BYTES, Bh + k0, D_MODEL, tid);
            cp_tile128(buf + 3*TILE_BYTES, Bl + k0, D_MODEL, tid);
            CP_COMMIT();
            asm volatile("cp.async.wait_group 1;" ::: "memory");
        } else {
            asm volatile("cp.async.wait_group 0;" ::: "memory");
        }
        __syncthreads();
        char* buf = smem + (ch&1)*(4*TILE_BYTES);
        hmma_3pass<8>(buf, buf + TILE_BYTES, buf + 2*TILE_BYTES, buf + 3*TILE_BYTES,
                      i0w, j0w, acc);
        __syncthreads();
    }

    if (z < 2) {
#pragma unroll
        for (int nt = 0; nt < 8; nt++) {
            const int col = n0 + j0w + nt*8 + tig*2;
            const int h = col >> 6, d = col & 63;
            const float b0v = bias[col], b1v = bias[col+1];
#pragma unroll
            for (int mt = 0; mt < 2; mt++) {
#pragma unroll
                for (int half = 0; half < 2; half++) {
                    const int token = m0 + i0w + mt*16 + gid + half*8;
                    const int b = token >> 11, s = token & 2047;
                    float v0 = acc[mt][nt][half*2+0] + b0v;
                    float v1 = acc[mt][nt][half*2+1] + b1v;
                    __nv_bfloat16 h0,l0,h1,l1;
                    bf16_split(v0,h0,l0); bf16_split(v1,h1,l1);
                    size_t o = ((size_t)(b*NHEAD + h)*SEQ + s)*DH + d;
                    if (z == 0) {
                        *reinterpret_cast<uint32_t*>(g_Qh + o) = pack2(h0,h1);
                        *reinterpret_cast<uint32_t*>(g_Ql + o) = pack2(l0,l1);
                    } else {
                        *reinterpret_cast<uint32_t*>(g_Kh + o) = pack2(h0,h1);
                        *reinterpret_cast<uint32_t*>(g_Kl + o) = pack2(l0,l1);
                    }
                }
            }
        }
    } else {
        char* sVh = smem;
        char* sVl = smem + VTILE;
#pragma unroll
        for (int nt = 0; nt < 8; nt++) {
            const int colL = j0w + nt*8 + tig*2;
            const int col = n0 + colL;
            const float b0v = bias[col], b1v = bias[col+1];
#pragma unroll
            for (int mt = 0; mt < 2; mt++) {
#pragma unroll
                for (int half = 0; half < 2; half++) {
                    const int tok = i0w + mt*16 + gid + half*8;
                    float v0 = acc[mt][nt][half*2+0] + b0v;
                    float v1 = acc[mt][nt][half*2+1] + b1v;
                    __nv_bfloat16 h0,l0,h1,l1;
                    bf16_split(v0,h0,l0); bf16_split(v1,h1,l1);
                    *reinterpret_cast<__nv_bfloat16*>(sVh + colL*VSTRIDE + tok*2)     = h0;
                    *reinterpret_cast<__nv_bfloat16*>(sVh + (colL+1)*VSTRIDE + tok*2) = h1;
                    *reinterpret_cast<__nv_bfloat16*>(sVl + colL*VSTRIDE + tok*2)     = l0;
                    *reinterpret_cast<__nv_bfloat16*>(sVl + (colL+1)*VSTRIDE + tok*2) = l1;
                }
            }
        }
        __syncthreads();
        const int b  = m0 >> 11, s0 = m0 & 2047;
        const int rsub = tid >> 4, cw = tid & 15;
#pragma unroll
        for (int it = 0; it < 8; it++) {
            const int rl = it*16 + rsub;
            const int col = n0 + rl;
            const int h = col >> 6, d = col & 63;
            uint4 vh = *reinterpret_cast<uint4*>(sVh + rl*VSTRIDE + cw*16);
            uint4 vl = *reinterpret_cast<uint4*>(sVl + rl*VSTRIDE + cw*16);
            size_t o = ((size_t)(b*NHEAD + h)*DH + d)*SEQ + s0 + cw*8;
            *reinterpret_cast<uint4*>(g_Vth + o) = vh;
            *reinterpret_cast<uint4*>(g_Vtl + o) = vl;
        }
    }
}

// ---------------------------------------------------------------------------
// Output projection
// ---------------------------------------------------------------------------
__global__ void __launch_bounds__(256)
oproj_kernel(const float* __restrict__ bo, float* __restrict__ out)
{
    extern __shared__ char smem[];
    const int tid = threadIdx.x, wid = tid >> 5;
    const int lane = tid & 31, gid = lane >> 2, tig = lane & 3;
    const int m0 = blockIdx.y*128, n0 = blockIdx.x*128;
    const int i0w = (wid & 3)*32, j0w = (wid >> 2)*64;

    const __nv_bfloat16* Ah = g_Xh + (size_t)m0*D_MODEL;
    const __nv_bfloat16* Al = g_Xl + (size_t)m0*D_MODEL;
    const __nv_bfloat16* Bh = g_Wh + (size_t)3*N2 + (size_t)n0*D_MODEL;
    const __nv_bfloat16* Bl = g_Wl + (size_t)3*N2 + (size_t)n0*D_MODEL;

    float acc[2][8][4];
#pragma unroll
    for (int mt = 0; mt < 2; mt++)
#pragma unroll
        for (int nt = 0; nt < 8; nt++)
#pragma unroll
            for (int q = 0; q < 4; q++) acc[mt][nt][q] = 0.f;

    {
        char* buf = smem;
        cp_tile128(buf,                Ah, D_MODEL, tid);
        cp_tile128(buf +   TILE_BYTES, Al, D_MODEL, tid);
        cp_tile128(buf + 2*TILE_BYTES, Bh, D_MODEL, tid);
        cp_tile128(buf + 3*TILE_BYTES, Bl, D_MODEL, tid);
        CP_COMMIT();
    }
    for (int ch = 0; ch < 8; ch++) {
        if (ch < 7) {
            char* buf = smem + ((ch+1)&1)*(4*TILE_BYTES);
            const int k0 = (ch+1)*64;
            cp_tile128(buf,                Ah + k0, D_MODEL, tid);
            cp_tile128(buf +   TILE_BYTES, Al + k0, D_MODEL, tid);
            cp_tile128(buf + 2*TILE_BYTES, Bh + k0, D_MODEL, tid);
            cp_tile128(buf + 3*TILE_BYTES, Bl + k0, D_MODEL, tid);
            CP_COMMIT();
            asm volatile("cp.async.wait_group 1;" ::: "memory");
        } else {
            asm volatile("cp.async.wait_group 0;" ::: "memory");
        }
        __syncthreads();
        char* buf = smem + (ch&1)*(4*TILE_BYTES);
        hmma_3pass<8>(buf, buf + TILE_BYTES, buf + 2*TILE_BYTES, buf + 3*TILE_BYTES,
                      i0w, j0w, acc);
        __syncthreads();
    }

#pragma unroll
    for (int nt = 0; nt < 8; nt++) {
        const int col = n0 + j0w + nt*8 + tig*2;
        const float b0v = bo[col], b1v = bo[col+1];
#pragma unroll
        for (int mt = 0; mt < 2; mt++) {
#pragma unroll
            for (int half = 0; half < 2; half++) {
                const int row = m0 + i0w + mt*16 + gid + half*8;
                float2 o;
                o.x = acc[mt][nt][half*2+0] + b0v;
                o.y = acc[mt][nt][half*2+1] + b1v;
                *reinterpret_cast<float2*>(out + (size_t)row*D_MODEL + col) = o;
            }
        }
    }
}

// ---------------------------------------------------------------------------
// Score kernel: masked, scaled fp32 scores into attn buffer.
// ---------------------------------------------------------------------------
#define SCORE_SMEM (4*TILE_BYTES)
__global__ void __launch_bounds__(256)
score_kernel(const int* __restrict__ mask, float* attn_arg)
{
    float* attn = attn_arg ? attn_arg : g_attn_fallback;
    extern __shared__ char smem[];
    char* sQ0 = smem;
    char* sQ1 = smem + TILE_BYTES;
    char* sK0 = smem + 2*TILE_BYTES;
    char* sK1 = smem + 3*TILE_BYTES;

    const int tid = threadIdx.x, wid = tid >> 5;
    const int lane = tid & 31, gid = lane >> 2, tig = lane & 3;
    const int bh = blockIdx.z, b = bh >> 3;
    const int m0 = blockIdx.y*128, n0 = blockIdx.x*128;
    const int i0w = (wid & 3)*32, j0w = (wid >> 2)*64;

    cp_tile128(sQ0, g_Qh + ((size_t)bh*SEQ + m0)*DH, DH, tid);
    cp_tile128(sQ1, g_Ql + ((size_t)bh*SEQ + m0)*DH, DH, tid);
    cp_tile128(sK0, g_Kh + ((size_t)bh*SEQ + n0)*DH, DH, tid);
    cp_tile128(sK1, g_Kl + ((size_t)bh*SEQ + n0)*DH, DH, tid);
    CP_COMMIT();
    asm volatile("cp.async.wait_group 0;" ::: "memory");
    __syncthreads();

    float acc[2][8][4];
#pragma unroll
    for (int mt = 0; mt < 2; mt++)
#pragma unroll
        for (int nt = 0; nt < 8; nt++)
#pragma unroll
            for (int q = 0; q < 4; q++) acc[mt][nt][q] = 0.f;

    hmma_3pass<8>(sQ0, sQ1, sK0, sK1, i0w, j0w, acc);

#pragma unroll
    for (int nt = 0; nt < 8; nt++) {
        const int col = n0 + j0w + nt*8 + tig*2;
        const int mv0 = __ldg(mask + b*SEQ + col);
        const int mv1 = __ldg(mask + b*SEQ + col + 1);
#pragma unroll
        for (int mt = 0; mt < 2; mt++) {
#pragma unroll
            for (int half = 0; half < 2; half++) {
                const int row = m0 + i0w + mt*16 + gid + half*8;
                float v0 = acc[mt][nt][half*2+0] * 0.125f;
                float v1 = acc[mt][nt][half*2+1] * 0.125f;
                if (mv0 == 0) v0 = -1.0e9f;
                if (mv1 == 0) v1 = -1.0e9f;
                float2 o; o.x = v0; o.y = v1;
                *reinterpret_cast<float2*>(attn + ((size_t)bh*SEQ + row)*SEQ + col) = o;
            }
        }
    }
}

// ---------------------------------------------------------------------------
// Softmax: normalize in place, emit bf16 hi/lo of attn.
// ---------------------------------------------------------------------------
__global__ void __launch_bounds__(256)
softmax_kernel(float* attn_arg)
{
    float* attn = attn_arg ? attn_arg : g_attn_fallback;
    __shared__ float red[8];
    const size_t row = blockIdx.x;
    float* p = attn + row * (size_t)SEQ;
    const int tid = threadIdx.x;

    float4 v0 = reinterpret_cast<float4*>(p)[2*tid + 0];
    float4 v1 = reinterpret_cast<float4*>(p)[2*tid + 1];

    float m = fmaxf(fmaxf(fmaxf(v0.x,v0.y), fmaxf(v0.z,v0.w)),
                    fmaxf(fmaxf(v1.x,v1.y), fmaxf(v1.z,v1.w)));
#pragma unroll
    for (int o = 16; o; o >>= 1) m = fmaxf(m, __shfl_xor_sync(0xffffffffu, m, o));
    if ((tid & 31) == 0) red[tid >> 5] = m;
    __syncthreads();
    m = red[0];
#pragma unroll
    for (int w = 1; w < 8; w++) m = fmaxf(m, red[w]);
    __syncthreads();

    v0.x = __expf(v0.x - m); v0.y = __expf(v0.y - m);
    v0.z = __expf(v0.z - m); v0.w = __expf(v0.w - m);
    v1.x = __expf(v1.x - m); v1.y = __expf(v1.y - m);
    v1.z = __expf(v1.z - m); v1.w = __expf(v1.w - m);

    float s = v0.x + v0.y + v0.z + v0.w + v1.x + v1.y + v1.z + v1.w;
#pragma unroll
    for (int o = 16; o; o >>= 1) s += __shfl_xor_sync(0xffffffffu, s, o);
    if ((tid & 31) == 0) red[tid >> 5] = s;
    __syncthreads();
    s = red[0];
#pragma unroll
    for (int w = 1; w < 8; w++) s += red[w];

    const float inv = 1.0f / s;
    v0.x *= inv; v0.y *= inv; v0.z *= inv; v0.w *= inv;
    v1.x *= inv; v1.y *= inv; v1.z *= inv; v1.w *= inv;
    reinterpret_cast<float4*>(p)[2*tid + 0] = v0;
    reinterpret_cast<float4*>(p)[2*tid + 1] = v1;

    float vf[8] = { v0.x, v0.y, v0.z, v0.w, v1.x, v1.y, v1.z, v1.w };
    __nv_bfloat16 hb[8], lb[8];
#pragma unroll
    for (int e = 0; e < 8; e++) bf16_split(vf[e], hb[e], lb[e]);
    size_t off = row * (size_t)SEQ + tid*8;
    *reinterpret_cast<uint4*>(g_Ah + off) = *reinterpret_cast<uint4*>(hb);
    *reinterpret_cast<uint4*>(g_Al + off) = *reinterpret_cast<uint4*>(lb);
}

// ---------------------------------------------------------------------------
// PV kernel: A+V double-buffered cp.async, 128x64 per CTA.
// ---------------------------------------------------------------------------
#define PVBUF   (2*TILE_BYTES + 2*BTILE64)   // 55296
#define PV_SMEM (2*PVBUF)                     // 110592
__global__ void __launch_bounds__(256)
pv_kernel()
{
    extern __shared__ char smem[];
    const int tid = threadIdx.x, wid = tid >> 5;
    const int lane = tid & 31, gid = lane >> 2, tig = lane & 3;
    const int bh = blockIdx.y, b = bh >> 3, h = bh & 7;
    const int m0 = blockIdx.x * 128;
    const int i0w = (wid & 3)*32, d0w = (wid >> 2)*32;

    const __nv_bfloat16* Ah = g_Ah + ((size_t)bh*SEQ + m0)*SEQ;
    const __nv_bfloat16* Al = g_Al + ((size_t)bh*SEQ + m0)*SEQ;
    const __nv_bfloat16* Bh = g_Vth + (size_t)bh*DH*SEQ;
    const __nv_bfloat16* Bl = g_Vtl + (size_t)bh*DH*SEQ;

    float acc[2][4][4];
#pragma unroll
    for (int mt = 0; mt < 2; mt++)
#pragma unroll
        for (int nt = 0; nt < 4; nt++)
#pragma unroll
            for (int q = 0; q < 4; q++) acc[mt][nt][q] = 0.f;

    {
        char* buf = smem;
        cp_tile128(buf,                         Ah, SEQ, tid);
        cp_tile128(buf + TILE_BYTES,            Al, SEQ, tid);
        cp_tile64 (buf + 2*TILE_BYTES,           Bh, SEQ, tid);
        cp_tile64 (buf + 2*TILE_BYTES + BTILE64, Bl, SEQ, tid);
        CP_COMMIT();
    }
    for (int ch = 0; ch < 32; ch++) {
        if (ch < 31) {
            char* buf = smem + ((ch+1)&1)*PVBUF;
            const int j0 = (ch+1)*64;
            cp_tile128(buf,                         Ah + j0, SEQ, tid);
            cp_tile128(buf + TILE_BYTES,            Al + j0, SEQ, tid);
            cp_tile64 (buf + 2*TILE_BYTES,           Bh + j0, SEQ, tid);
            cp_tile64 (buf + 2*TILE_BYTES + BTILE64, Bl + j0, SEQ, tid);
            CP_COMMIT();
            asm volatile("cp.async.wait_group 1;" ::: "memory");
        } else {
            asm volatile("cp.async.wait_group 0;" ::: "memory");
        }
        __syncthreads();
        char* buf = smem + (ch&1)*PVBUF;
        hmma_3pass<4>(buf, buf + TILE_BYTES, buf + 2*TILE_BYTES, buf + 2*TILE_BYTES + BTILE64,
                      i0w, d0w, acc);
        __syncthreads();
    }

#pragma unroll
    for (int nt = 0; nt < 4; nt++) {
        const int d = d0w + nt*8 + tig*2;
#pragma unroll
        for (int mt = 0; mt < 2; mt++) {
#pragma unroll
            for (int half = 0; half < 2; half++) {
                const int row = m0 + i0w + mt*16 + gid + half*8;
                float v0 = acc[mt][nt][half*2+0];
                float v1 = acc[mt][nt][half*2+1];
                __nv_bfloat16 h0,l0,h1,l1;
                bf16_split(v0,h0,l0); bf16_split(v1,h1,l1);
                size_t o = ((size_t)(b*SEQ + row))*D_MODEL + h*DH + d;
                *reinterpret_cast<uint32_t*>(g_Xh + o) = pack2(h0,h1);
                *reinterpret_cast<uint32_t*>(g_Xl + o) = pack2(l0,l1);
            }
        }
    }
}

// ---------------------------------------------------------------------------
extern "C" void kernel_launch(void* const* d_in, const int* in_sizes, int n_in,
                              void* d_out, int out_size)
{
    const float* query = (const float*)d_in[0];
    const float* key   = (const float*)d_in[1];
    const float* value = (const float*)d_in[2];
    const int*   mask  = (const int*)  d_in[3];
    const float* Wq    = (const float*)d_in[4];
    const float* bq    = (const float*)d_in[5];
    const float* Wk    = (const float*)d_in[6];
    const float* bk    = (const float*)d_in[7];
    const float* Wv    = (const float*)d_in[8];
    const float* bv    = (const float*)d_in[9];
    const float* Wo    = (const float*)d_in[10];
    const float* bo    = (const float*)d_in[11];

    float* out = (float*)d_out;
    float* attn_arg = ((long long)out_size >= (long long)OUT_ELEMS + ATTN_ELEMS)
                      ? (out + OUT_ELEMS) : nullptr;

    cudaFuncSetAttribute(qkv_proj_kernel, cudaFuncAttributeMaxDynamicSharedMemorySize, PROJ_SMEM);
    cudaFuncSetAttribute(oproj_kernel,    cudaFuncAttributeMaxDynamicSharedMemorySize, PROJ_SMEM);
    cudaFuncSetAttribute(score_kernel,    cudaFuncAttributeMaxDynamicSharedMemorySize, SCORE_SMEM);
    cudaFuncSetAttribute(pv_kernel,       cudaFuncAttributeMaxDynamicSharedMemorySize, PV_SMEM);

    dim3 blk(256);
    split_kernel   <<<dim3(256, 7), blk>>>(query, key, value, Wq, Wk, Wv, Wo);
    qkv_proj_kernel<<<dim3(4, 32, 3), blk, PROJ_SMEM>>>(bq, bk, bv);
    score_kernel   <<<dim3(16, 16, 16), blk, SCORE_SMEM>>>(mask, attn_arg);
    softmax_kernel <<<dim3(NBH*SEQ), blk>>>(attn_arg);
    pv_kernel      <<<dim3(16, 16), blk, PV_SMEM>>>();
    oproj_kernel   <<<dim3(4, 32), blk, PROJ_SMEM>>>(bo, out);
}